// round 11
// baseline (speedup 1.0000x reference)
#include <cuda_runtime.h>
#include <cub/cub.cuh>
#include <cstdint>

// Problem constants (B=8, L=1e6, C=4 -> size=1349)
#define SPIRAL_SIZE 1349
#define HALF        674
#define NCELL       (SPIRAL_SIZE * SPIRAL_SIZE)   // 1,819,801 < 2^21
#define SIGLEN      1000000
#define NBATCH      8

#define PI_F 3.14159274101257324f   // fl(pi)

// Validity cutoff (validated rel_err==0.0): rings 0..564 cover all ranks < 1e6.
#define KMAX   564
#define NRV    (KMAX + 1)           // 565 valid rings

#define RBKT   2048                 // smem buckets per ring
#define RT     512                  // ring_rank threads
#define SLOTCAP 3968                // >= max ring pop (~3544 + fluctuation)

#define STAGECAP 1310720            // > seg_off(NRV) ~ 1,292,300
#define HALF_ROWS   (HALF + 1)
#define HALF_CELLS  (HALF_ROWS * SPIRAL_SIZE)  // 910,575

__device__ uint32_t           g_ringCount[NRV];
__device__ unsigned long long g_staged[STAGECAP];
__device__ uint32_t           g_rank[NCELL];

extern "C" __device__ float __nv_atan2f(float, float);

// JAX acos: acos(x) = 2*atan2(sqrt(1-x*x), 1+x); exact pi at x==-1.
__device__ __forceinline__ float acos_jax(float xq) {
    if (xq == -1.0f) return PI_F;
    float t  = __fsub_rn(1.0f, __fmul_rn(xq, xq));
    float sq = __fsqrt_rn(t);
    return __fmul_rn(2.0f, __nv_atan2f(sq, __fadd_rn(1.0f, xq)));
}

// Analytic ring-segment offset: cumulative area pi*k^2 plus 512/ring slack.
// seg_off(k+1)-seg_off(k) ~ 2*pi*k + 512 >= ring population (fluct << 512).
__device__ __forceinline__ uint32_t seg_off(int k) {
    return (uint32_t)(3.141592653589793 * (double)k * (double)k + 0.5)
         + ((uint32_t)k << 9);
}

// Per-ring bucket mapping (validated). Keys of ring k lie in [T-pi, T+pi],
// T = fl(2k*pi); bound +-3.2 guarantees containment. (kb-lo)>>sh < 2048.
__device__ __forceinline__ void ring_map(int k, uint32_t& lo, int& sh) {
    float T   = __fmul_rn((float)(2 * k), PI_F);
    float lof = fmaxf(__fsub_rn(T, 3.2f), 0.0f);
    float hif = __fadd_rn(T, 3.2f);
    lo = __float_as_uint(lof);
    uint32_t span = __float_as_uint(hif) - lo;
    int bn = 32 - __clz(span | 1);
    sh = (bn > 11) ? (bn - 11) : 0;
}

// ---------------------------------------------------------------------------
// K1: dense over x2>=0 half-plane; one thread -> key for its cell AND mirror
// (bit-exact: r, xq, A identical; phi*sign(x2) is an exact sign flip).
// Appends packed (kb<<21 | s) into ring k's segment; mirror pair shares one
// atomicAdd(+2) since both cells are in the same ring.
// ---------------------------------------------------------------------------
__global__ __launch_bounds__(256) void key_kernel() {
    int tid = blockIdx.x * blockDim.x + threadIdx.x;
    if (tid >= HALF_CELLS) return;
    int di = tid / SPIRAL_SIZE;
    int j  = tid - di * SPIRAL_SIZE;
    int i  = HALF + di;

    float x1 = (float)(j - HALF);
    float x2 = (float)di;
    float rr = __fadd_rn(__fmul_rn(x1, x1), __fmul_rn(x2, x2));
    float r  = __fsqrt_rn(rr);
    int   k  = (int)rintf(r);
    if (k > KMAX) return;

    float T = __fmul_rn(__fmul_rn(rintf(r), 2.0f), PI_F);
    uint32_t s = (uint32_t)(i * SPIRAL_SIZE + j);

    if (di == 0) {
        // x2 == 0 row: phi = 0 (NaN-fixed center), +pi if x1 < 0.
        float phi = (x1 < 0.0f) ? PI_F : 0.0f;
        uint32_t kb  = __float_as_uint(__fadd_rn(T, phi));
        uint32_t pos = seg_off(k) + atomicAdd(&g_ringCount[k], 1u);
        g_staged[pos] = ((unsigned long long)kb << 21) | s;
        return;
    }

    float A = acos_jax(__fdiv_rn(x1, r));      // finite: r > 0 here
    uint32_t kb  = __float_as_uint(__fadd_rn(T, A));     // phi = +A
    uint32_t kbm = __float_as_uint(__fadd_rn(T, -A));    // mirror: phi = -A
    uint32_t sm  = (uint32_t)((2 * HALF - i) * SPIRAL_SIZE + j);

    uint32_t pos = seg_off(k) + atomicAdd(&g_ringCount[k], 2u);
    g_staged[pos]     = ((unsigned long long)kb << 21) | s;
    g_staged[pos + 1] = ((unsigned long long)kbm << 21) | sm;
}

// ---------------------------------------------------------------------------
// K2: one block per ring. In-SM counting-sort rank:
//   ringStart = block-reduce of ringCount[0..k)
//   smem 2048-bucket hist -> block scan -> smem bucket scatter ->
//   rank = bucketStart + #{bucket peers with smaller packed value}
// Packed compare makes float-key ties index-stable == jnp.argsort (validated).
// Writes g_rank[s] = ringStart + within-ring rank.
// ---------------------------------------------------------------------------
__global__ __launch_bounds__(RT) void ring_rank_kernel() {
    extern __shared__ unsigned char dyn[];
    unsigned long long* slots = (unsigned long long*)dyn;          // SLOTCAP*8
    uint32_t* hist   = (uint32_t*)(dyn + SLOTCAP * 8);             // RBKT*4
    uint32_t* boff   = hist + RBKT;                                // RBKT*4
    uint32_t* cursor = boff + RBKT;                                // RBKT*4

    typedef cub::BlockScan<uint32_t, RT>  BS;
    typedef cub::BlockReduce<uint32_t, RT> BR;
    __shared__ union { typename BS::TempStorage scan;
                       typename BR::TempStorage red; } tmp;
    __shared__ uint32_t s_ringStart;

    const int k = blockIdx.x;
    const int t = threadIdx.x;

    // Ring start = total population of rings < k.
    uint32_t my = 0;
    for (int m = t; m < k; m += RT) my += g_ringCount[m];
    uint32_t rs = BR(tmp.red).Sum(my);
    if (t == 0) s_ringStart = rs;

    for (int b = t; b < RBKT; b += RT) hist[b] = 0;
    __syncthreads();

    const uint32_t n    = g_ringCount[k];
    const uint32_t base = seg_off(k);
    uint32_t lo; int sh;
    ring_map(k, lo, sh);

    // Pass 1: histogram (segment is L2-hot from key_kernel).
    for (uint32_t p = t; p < n; p += RT) {
        unsigned long long e = g_staged[base + p];
        uint32_t b = ((uint32_t)(e >> 21) - lo) >> sh;
        atomicAdd(&hist[b], 1u);
    }
    __syncthreads();

    // Exclusive scan of 2048 buckets (512 threads x 4).
    uint32_t c0 = hist[t * 4], c1 = hist[t * 4 + 1];
    uint32_t c2 = hist[t * 4 + 2], c3 = hist[t * 4 + 3];
    uint32_t ex;
    BS(tmp.scan).ExclusiveSum(c0 + c1 + c2 + c3, ex);
    boff[t * 4]     = ex; cursor[t * 4]     = ex; ex += c0;
    boff[t * 4 + 1] = ex; cursor[t * 4 + 1] = ex; ex += c1;
    boff[t * 4 + 2] = ex; cursor[t * 4 + 2] = ex; ex += c2;
    boff[t * 4 + 3] = ex; cursor[t * 4 + 3] = ex;
    __syncthreads();

    // Pass 2: bucket scatter into slots.
    for (uint32_t p = t; p < n; p += RT) {
        unsigned long long e = g_staged[base + p];
        uint32_t b   = ((uint32_t)(e >> 21) - lo) >> sh;
        uint32_t pos = atomicAdd(&cursor[b], 1u);
        if (pos < SLOTCAP) slots[pos] = e;
    }
    __syncthreads();

    // Pass 3: exact rank among bucket peers; write global rank.
    const uint32_t ringStart = s_ringStart;
    for (uint32_t p = t; p < n; p += RT) {
        unsigned long long e = slots[p];
        uint32_t b   = ((uint32_t)(e >> 21) - lo) >> sh;
        uint32_t st  = boff[b];
        uint32_t cnt = hist[b];
        uint32_t rank = st;
        if (cnt > 1) {
            for (uint32_t q = st; q < st + cnt; q++)
                rank += (slots[q] < e) ? 1u : 0u;
        }
        g_rank[(uint32_t)(e & 0x1FFFFFu)] = ringStart + rank;
    }
}

// ---------------------------------------------------------------------------
// K3: gather (R2's measured-fastest form). Linear coalesced writes; one
// coalesced rank read; k-guard zeroes invalid rings (their g_rank is never
// written -- the guard short-circuits, deterministic).
// ---------------------------------------------------------------------------
__global__ __launch_bounds__(256) void gather_kernel(
        const float4* __restrict__ in, float4* __restrict__ out,
        const uint32_t* __restrict__ rank_arr) {
    int s = blockIdx.x * blockDim.x + threadIdx.x;
    if (s >= NCELL) return;
    int i = s / SPIRAL_SIZE, j = s - i * SPIRAL_SIZE;
    float x1 = (float)(j - HALF), x2 = (float)(i - HALF);
    float r = __fsqrt_rn(__fadd_rn(__fmul_rn(x1, x1), __fmul_rn(x2, x2)));
    int k = (int)rintf(r);

    uint32_t rank = rank_arr[s];
    bool valid = (k <= KMAX) && (rank < (uint32_t)SIGLEN);

    float4 z = make_float4(0.0f, 0.0f, 0.0f, 0.0f);
#pragma unroll
    for (int b = 0; b < NBATCH; b++) {
        float4 w = z;
        if (valid) w = __ldg(&in[(size_t)b * SIGLEN + rank]);
        __stcs(&out[(size_t)b * NCELL + s], w);
    }
}

extern "C" void kernel_launch(void* const* d_in, const int* in_sizes, int n_in,
                              void* d_out, int out_size) {
    (void)in_sizes; (void)n_in; (void)out_size;

    void *cntp, *rankp;
    cudaGetSymbolAddress(&cntp,  g_ringCount);
    cudaGetSymbolAddress(&rankp, g_rank);

    // Dynamic smem: slots + hist + boff + cursor.
    const int DYN = SLOTCAP * 8 + 3 * RBKT * 4;   // 31,744 + 24,576 = 56,320 B
    static int attr_set = 0;
    cudaFuncSetAttribute(ring_rank_kernel,
                         cudaFuncAttributeMaxDynamicSharedMemorySize, DYN);
    (void)attr_set;

    cudaMemsetAsync(cntp, 0, NRV * sizeof(uint32_t), (cudaStream_t)0);

    key_kernel<<<(HALF_CELLS + 255) / 256, 256>>>();
    ring_rank_kernel<<<NRV, RT, DYN>>>();
    gather_kernel<<<(NCELL + 255) / 256, 256>>>(
        (const float4*)d_in[0], (float4*)d_out, (const uint32_t*)rankp);
}